// round 14
// baseline (speedup 1.0000x reference)
#include <cuda_runtime.h>

// Problem constants
#define B 256
#define N_IN 100          // input retrieval dim
#define R 80              // RETRIEVAL_NUM
#define D 768             // feature dim
#define ROWQ (D / 4)      // 192 float4s per feature row
#define THRESH 0.5f

// Output layout (flattened concatenation, all float32):
//   vis_packed : B*R*D   (f4 rows [0, B*R))
//   txt_packed : B*R*D   (f4 rows [B*R, 2*B*R))
//   text_mask  : B*(R+1)
//   img_mask   : B*(R+1)
//   rr_mod     : B*R
//   labels     : B*R
#define OFF_TMASK ((size_t)2 * B * R * D)
#define OFF_IMASK (OFF_TMASK + (size_t)B * (R + 1))
#define OFF_RRMOD (OFF_IMASK + (size_t)B * (R + 1))
#define OFF_LBL   (OFF_RRMOD + (size_t)B * R)

// Fused geometry:
//   Per batch: 2*R rows * 6 chunks/row = 960 chunks of 32 float4 (512B).
//   120 warps per batch, 8 chunks per warp (2 groups of 4 independent chains).
//   3840 gather blocks (8 warps each) + 8 meta blocks for small outputs.
#define GATHER_BLOCKS 3840
#define META_BLOCKS 8
#define THREADS 256
#define WPBATCH 120
#define CPR 6                         // chunks per row (192/32)
#define NROW_HALF ((unsigned)B * R)   // 20480

// position of the j-th (0-indexed) set bit of m (assumes it exists)
__device__ __forceinline__ int nth_set_bit(unsigned m, int j) {
    int p = 0, c;
    c = __popc(m & 0xFFFFu); if (j >= c) { j -= c; p = 16; m >>= 16; }
    c = __popc(m & 0xFFu);   if (j >= c) { j -= c; p += 8; m >>= 8; }
    c = __popc(m & 0xFu);    if (j >= c) { j -= c; p += 4; m >>= 4; }
    c = __popc(m & 0x3u);    if (j >= c) { j -= c; p += 2; m >>= 2; }
    c = (int)(m & 1u);       if (j >= c) { p += 1; }
    return p;
}

// position (0..79) of the t-th selection across the 3 ballot masks
__device__ __forceinline__ int sel_pos(int t, unsigned m0, unsigned m1,
                                       unsigned m2, int c0, int c01) {
    if (t < c0)  return nth_set_bit(m0, t);
    if (t < c01) return 32 + nth_set_bit(m1, t - c0);
    return 64 + nth_set_bit(m2, t - c01);
}

__global__ void __launch_bounds__(THREADS)
fused_pack(const float4* __restrict__ vis,
           const float4* __restrict__ txt,
           const float* __restrict__ rrcp,
           const float* __restrict__ labels_in,
           float* __restrict__ out) {
    const unsigned FULL = 0xFFFFFFFFu;
    const unsigned blk = blockIdx.x;
    const int lane = threadIdx.x & 31;
    const int warp = threadIdx.x >> 5;

    if (blk < GATHER_BLOCKS) {
        // ---------------- gather path (one batch per warp) ----------------
        const unsigned w = blk * 8 + warp;          // global warp id
        const unsigned b = w / WPBATCH;             // batch
        const unsigned wloc = w - b * WPBATCH;      // 0..119: chunk lane within batch
        const unsigned base = b * N_IN;

        // warp-private compaction: 3 ballots over 80 RRCP values
        float r0 = rrcp[base + lane];
        float r1 = rrcp[base + 32 + lane];
        float r2 = (lane < 16) ? rrcp[base + 64 + lane] : 0.0f;
        unsigned m0 = __ballot_sync(FULL, r0 > THRESH);
        unsigned m1 = __ballot_sync(FULL, r1 > THRESH);
        unsigned m2 = __ballot_sync(FULL, (lane < 16) && (r2 > THRESH));
        const int c0  = __popc(m0);
        const int c01 = c0 + __popc(m1);
        const int cnt = c01 + __popc(m2);

        // Selection table across 3 registers:
        //   s0: lane l -> source row of selection l        (l      < cnt)
        //   s1: lane l -> source row of selection l+32     (l+32   < cnt)
        //   s2: lane l -> source row of selection l+64     (l+64   < cnt)
        int s0 = 0, s1 = 0, s2 = 0;
        if (lane < cnt)
            s0 = (int)base + sel_pos(lane, m0, m1, m2, c0, c01);
        if (lane + 32 < cnt)
            s1 = (int)base + sel_pos(lane + 32, m0, m1, m2, c0, c01);
        if (lane + 64 < cnt)
            s2 = (int)base + sel_pos(lane + 64, m0, m1, m2, c0, c01);

        float4* out_f4 = (float4*)out;
        const unsigned out_b = b * R * ROWQ;        // batch base (f4 elements)

        #pragma unroll
        for (int g = 0; g < 2; ++g) {
            unsigned dst[4];
            float4 v[4];
            #pragma unroll
            for (int k = 0; k < 4; ++k) {
                const unsigned c = wloc + (unsigned)(g * 4 + k) * WPBATCH; // chunk 0..959
                const unsigned lrow = c / CPR;        // 0..159 (warp-uniform)
                const unsigned off  = (c - lrow * CPR) * 32 + lane;
                const unsigned wh = (lrow >= R) ? 1u : 0u;
                const unsigned j = lrow - (wh ? R : 0u);     // 0..79, warp-uniform
                dst[k] = (wh ? NROW_HALF * ROWQ : 0u) + out_b + j * ROWQ + off;
                // uniform register select + single shfl broadcast
                const int reg = (j < 32) ? s0 : (j < 64) ? s1 : s2;
                const int srow = __shfl_sync(FULL, reg, (int)(j & 31u));
                if ((int)j < cnt) {
                    const float4* s = wh ? txt : vis;
                    v[k] = s[(size_t)srow * ROWQ + off];
                } else {
                    v[k] = make_float4(0.0f, 0.0f, 0.0f, 0.0f);
                }
            }
            #pragma unroll
            for (int k = 0; k < 4; ++k) {
                out_f4[dst[k]] = v[k];
            }
        }
    } else {
        // ---------------- small outputs (8 blocks, 4 batches per warp) ----
        const int mb = blk - GATHER_BLOCKS;          // 0..7
        #pragma unroll
        for (int i = 0; i < 4; ++i) {
            const int b = (mb * 8 + warp) * 4 + i;
            const int base = b * N_IN;

            float r0 = rrcp[base + lane];
            float r1 = rrcp[base + 32 + lane];
            float r2 = (lane < 16) ? rrcp[base + 64 + lane] : 0.0f;

            unsigned m0 = __ballot_sync(FULL, r0 > THRESH);
            unsigned m1 = __ballot_sync(FULL, r1 > THRESH);
            unsigned m2 = __ballot_sync(FULL, (lane < 16) && (r2 > THRESH));
            const int cnt = __popc(m0) + __popc(m1) + __popc(m2);

            // zero_rows: all rr < 0.5 (rr_mod nonzero iff rr >= 0.5)
            unsigned nz = __ballot_sync(FULL, r0 >= THRESH) |
                          __ballot_sync(FULL, r1 >= THRESH) |
                          __ballot_sync(FULL, (lane < 16) && (r2 >= THRESH));
            const int all_below = (nz == 0u);

            // rr_mod + labels (chunks at lane, 32+lane, 64+lane[<16])
            float rm0 = (r0 < THRESH) ? 0.0f : r0;
            if (lane == 0 && all_below) rm0 = 1.0f;
            out[OFF_RRMOD + (size_t)b * R + lane] = rm0;
            out[OFF_LBL   + (size_t)b * R + lane] = labels_in[base + lane];

            float rm1 = (r1 < THRESH) ? 0.0f : r1;
            out[OFF_RRMOD + (size_t)b * R + 32 + lane] = rm1;
            out[OFF_LBL   + (size_t)b * R + 32 + lane] = labels_in[base + 32 + lane];

            if (lane < 16) {
                float rm2 = (r2 < THRESH) ? 0.0f : r2;
                out[OFF_RRMOD + (size_t)b * R + 64 + lane] = rm2;
                out[OFF_LBL   + (size_t)b * R + 64 + lane] = labels_in[base + 64 + lane];
            }

            // masks (81 entries)
            #pragma unroll
            for (int cidx = 0; cidx < 3; ++cidx) {
                int p = cidx * 32 + lane;
                if (p <= R) {
                    float tm = (p <= cnt) ? 1.0f : 0.0f;
                    out[OFF_TMASK + (size_t)b * (R + 1) + p] = tm;
                    float im = (b == B - 1) ? tm : 1.0f;
                    out[OFF_IMASK + (size_t)b * (R + 1) + p] = im;
                }
            }
        }
    }
}

// ---------------------------------------------------------------------------
extern "C" void kernel_launch(void* const* d_in, const int* in_sizes, int n_in,
                              void* d_out, int out_size) {
    // Input order per metadata:
    // 0: mean_pooling_vec (unused)
    // 1: merge_text_vec (unused)
    // 2: retrieved_visual_feature_embedding_cls (B,N,1,D)
    // 3: retrieved_textual_feature_embedding   (B,N,1,D)
    // 4: retrieved_label_list (B,N)
    // 5: RRCP (B,N)
    const float* vis    = (const float*)d_in[2];
    const float* txt    = (const float*)d_in[3];
    const float* labels = (const float*)d_in[4];
    const float* rrcp   = (const float*)d_in[5];
    float* out = (float*)d_out;

    fused_pack<<<GATHER_BLOCKS + META_BLOCKS, THREADS>>>(
        (const float4*)vis, (const float4*)txt, rrcp, labels, out);
}